// round 5
// baseline (speedup 1.0000x reference)
#include <cuda_runtime.h>
#include <cstdint>

#define BATCH   4096
#define IN_DIM  4096
#define OUT_DIM 4096
#define BN_EPS  1e-3f

#define XS_STRIDE 68   // words; conflict-free A frags
#define BS_STRIDE 72   // words; conflict-free B frags

// SMEM (dynamic): Xs[128][68] u32 | Bs[64][72] u32 | sc_s[64] | sh_s[64]
#define XS_OFF   0
#define BS_OFF   (128 * XS_STRIDE * 4)
#define SC_OFF   (BS_OFF + 64 * BS_STRIDE * 4)
#define SH_OFF   (SC_OFF + 64 * 4)
#define SMEM_TOTAL (SH_OFF + 64 * 4)

// ---------------- scratch ---------------------------------------------------
__device__ float g_sum[OUT_DIM];
__device__ float g_sumsq[OUT_DIM];
__device__ float g_scale[OUT_DIM];
__device__ float g_shift[OUT_DIM];

__device__ __forceinline__ uint32_t f2tf32(float f) {
    uint32_t r;
    asm("cvt.rna.tf32.f32 %0, %1;" : "=r"(r) : "f"(f));
    return r;
}

__device__ __forceinline__ void mma_tf32(float c[4], const uint32_t a[4],
                                         const uint32_t b[2]) {
    asm volatile(
        "mma.sync.aligned.m16n8k8.row.col.f32.tf32.tf32.f32 "
        "{%0,%1,%2,%3}, {%4,%5,%6,%7}, {%8,%9}, {%0,%1,%2,%3};"
        : "+f"(c[0]), "+f"(c[1]), "+f"(c[2]), "+f"(c[3])
        : "r"(a[0]), "r"(a[1]), "r"(a[2]), "r"(a[3]), "r"(b[0]), "r"(b[1]));
}

// Shared GEMM body: loads tiles, runs mainloop, leaves result in c[2][8][4].
template <bool LOAD_SCALES>
__device__ __forceinline__ void gemm_body(
    const float* __restrict__ x, const float* __restrict__ w,
    char* smem, int s, int rowBase, float c[2][8][4])
{
    uint32_t* Xs = (uint32_t*)(smem + XS_OFF);
    uint32_t* Bs = (uint32_t*)(smem + BS_OFF);
    const int tid  = threadIdx.x;
    const int wid  = tid >> 5;
    const int lane = tid & 31;
    const int gid  = lane >> 2;
    const int tig  = lane & 3;

    #pragma unroll
    for (int i = 0; i < 16; i++) {
        int idx = i * 128 + tid;
        int row = idx >> 4;
        int c4  = idx & 15;
        float4 v = *(const float4*)(x + (size_t)(rowBase + row) * IN_DIM + s * 64 + c4 * 4);
        uint32_t* d = Xs + row * XS_STRIDE + c4 * 4;
        d[0] = f2tf32(v.x); d[1] = f2tf32(v.y); d[2] = f2tf32(v.z); d[3] = f2tf32(v.w);
    }
    #pragma unroll
    for (int i = 0; i < 8; i++) {
        int idx = i * 128 + tid;
        int k  = idx >> 4;
        int c4 = idx & 15;
        float4 v = *(const float4*)(w + (size_t)(s * 64 + k) * OUT_DIM + s * 64 + c4 * 4);
        uint32_t* d = Bs + k * BS_STRIDE + c4 * 4;
        d[0] = f2tf32(v.x); d[1] = f2tf32(v.y); d[2] = f2tf32(v.z); d[3] = f2tf32(v.w);
    }
    if (LOAD_SCALES && tid < 32) {
        float4 v = (tid < 16)
            ? *(const float4*)(g_scale + s * 64 + tid * 4)
            : *(const float4*)(g_shift + s * 64 + (tid - 16) * 4);
        *(float4*)(smem + SC_OFF + tid * 16) = v;
    }
    __syncthreads();

    #pragma unroll
    for (int mc = 0; mc < 2; mc++)
        #pragma unroll
        for (int nc = 0; nc < 8; nc++)
            #pragma unroll
            for (int q = 0; q < 4; q++)
                c[mc][nc][q] = 0.f;

    #pragma unroll
    for (int kc = 0; kc < 8; kc++) {
        const int k0 = kc * 8;
        uint32_t a[2][4];
        #pragma unroll
        for (int mc = 0; mc < 2; mc++) {
            int r = wid * 32 + mc * 16 + gid;
            a[mc][0] = Xs[r * XS_STRIDE + k0 + tig];
            a[mc][1] = Xs[(r + 8) * XS_STRIDE + k0 + tig];
            a[mc][2] = Xs[r * XS_STRIDE + k0 + tig + 4];
            a[mc][3] = Xs[(r + 8) * XS_STRIDE + k0 + tig + 4];
        }
        uint32_t b[8][2];
        #pragma unroll
        for (int nc = 0; nc < 8; nc++) {
            b[nc][0] = Bs[(k0 + tig) * BS_STRIDE + nc * 8 + gid];
            b[nc][1] = Bs[(k0 + tig + 4) * BS_STRIDE + nc * 8 + gid];
        }
        #pragma unroll
        for (int mc = 0; mc < 2; mc++)
            #pragma unroll
            for (int nc = 0; nc < 8; nc++)
                mma_tf32(c[mc][nc], a[mc], b[nc]);
    }
}

// ---------------- kernels ---------------------------------------------------
__global__ void zero_stats_kernel() {
    int i = blockIdx.x * blockDim.x + threadIdx.x;
    if (i < OUT_DIM) { g_sum[i] = 0.f; g_sumsq[i] = 0.f; }
}

// Pass A: GEMM -> column stats only (no output store). Bias cancels in BN.
__global__ __launch_bounds__(128) void stats_kernel(
    const float* __restrict__ x, const float* __restrict__ w)
{
    extern __shared__ char smem[];
    const int tid  = threadIdx.x;
    const int lane = tid & 31;
    const int gid  = lane >> 2;
    const int tig  = lane & 3;
    const int s       = blockIdx.y;
    const int rowBase = blockIdx.x * 128;

    float c[2][8][4];
    gemm_body<false>(x, w, smem, s, rowBase, c);

    const int colBase = s * 64;
    #pragma unroll
    for (int nc = 0; nc < 8; nc++) {
        const int col = nc * 8 + 2 * tig;
        float s0 = c[0][nc][0] + c[0][nc][2] + c[1][nc][0] + c[1][nc][2];
        float s1 = c[0][nc][1] + c[0][nc][3] + c[1][nc][1] + c[1][nc][3];
        float q0 = fmaf(c[0][nc][0], c[0][nc][0], fmaf(c[0][nc][2], c[0][nc][2],
                   fmaf(c[1][nc][0], c[1][nc][0], c[1][nc][2] * c[1][nc][2])));
        float q1 = fmaf(c[0][nc][1], c[0][nc][1], fmaf(c[0][nc][3], c[0][nc][3],
                   fmaf(c[1][nc][1], c[1][nc][1], c[1][nc][3] * c[1][nc][3])));
        #pragma unroll
        for (int m = 4; m < 32; m <<= 1) {
            s0 += __shfl_xor_sync(0xffffffffu, s0, m);
            s1 += __shfl_xor_sync(0xffffffffu, s1, m);
            q0 += __shfl_xor_sync(0xffffffffu, q0, m);
            q1 += __shfl_xor_sync(0xffffffffu, q1, m);
        }
        if (gid == 0) {
            atomicAdd(&g_sum[colBase + col],       s0);
            atomicAdd(&g_sum[colBase + col + 1],   s1);
            atomicAdd(&g_sumsq[colBase + col],     q0);
            atomicAdd(&g_sumsq[colBase + col + 1], q1);
        }
    }
}

__global__ void finalize_kernel(const float* __restrict__ gamma,
                                const float* __restrict__ beta) {
    int j = blockIdx.x * blockDim.x + threadIdx.x;
    if (j < OUT_DIM) {
        const float invB = 1.0f / (float)BATCH;
        float mean = g_sum[j] * invB;                       // mean of raw gemm
        float var  = fmaxf(g_sumsq[j] * invB - mean * mean, 0.f);
        float sc   = gamma[j] * rsqrtf(var + BN_EPS);
        g_scale[j] = sc;
        g_shift[j] = fmaf(-mean, sc, beta[j]);              // bias cancels
    }
}

// Pass B: recompute GEMM, normalize + ReLU, coalesced store via SMEM stage.
__global__ __launch_bounds__(128) void apply_kernel(
    const float* __restrict__ x, const float* __restrict__ w,
    float* __restrict__ out)
{
    extern __shared__ char smem[];
    const int tid  = threadIdx.x;
    const int wid  = tid >> 5;
    const int lane = tid & 31;
    const int gid  = lane >> 2;
    const int tig  = lane & 3;
    const int s       = blockIdx.y;
    const int rowBase = blockIdx.x * 128;

    float c[2][8][4];
    gemm_body<true>(x, w, smem, s, rowBase, c);

    const float* sc_s = (const float*)(smem + SC_OFF);
    const float* sh_s = (const float*)(smem + SH_OFF);

    __syncthreads();   // done reading Xs/Bs; reuse as stage
    float* stage = (float*)(smem + XS_OFF);
    #pragma unroll
    for (int nc = 0; nc < 8; nc++) {
        const int col = nc * 8 + 2 * tig;
        const float scx = sc_s[col], scy = sc_s[col + 1];
        const float shx = sh_s[col], shy = sh_s[col + 1];
        #pragma unroll
        for (int mc = 0; mc < 2; mc++) {
            const int r = wid * 32 + mc * 16 + gid;
            stage[r * XS_STRIDE + col]           = fmaxf(fmaf(c[mc][nc][0], scx, shx), 0.f);
            stage[r * XS_STRIDE + col + 1]       = fmaxf(fmaf(c[mc][nc][1], scy, shy), 0.f);
            stage[(r + 8) * XS_STRIDE + col]     = fmaxf(fmaf(c[mc][nc][2], scx, shx), 0.f);
            stage[(r + 8) * XS_STRIDE + col + 1] = fmaxf(fmaf(c[mc][nc][3], scy, shy), 0.f);
        }
    }
    __syncthreads();

    #pragma unroll
    for (int i = 0; i < 16; i++) {
        int idx = i * 128 + tid;
        int row = idx >> 4;
        int c4  = idx & 15;
        float4 v = *(const float4*)(stage + row * XS_STRIDE + c4 * 4);
        *(float4*)(out + (size_t)(rowBase + row) * OUT_DIM + s * 64 + c4 * 4) = v;
    }
}

extern "C" void kernel_launch(void* const* d_in, const int* in_sizes, int n_in,
                              void* d_out, int out_size) {
    const float* x     = (const float*)d_in[0];
    const float* w     = (const float*)d_in[1];
    const float* gamma = (const float*)d_in[3];
    const float* beta  = (const float*)d_in[4];
    float* out = (float*)d_out;

    static bool attr_set = false;
    if (!attr_set) {
        cudaFuncSetAttribute(stats_kernel,
                             cudaFuncAttributeMaxDynamicSharedMemorySize, SMEM_TOTAL);
        cudaFuncSetAttribute(apply_kernel,
                             cudaFuncAttributeMaxDynamicSharedMemorySize, SMEM_TOTAL);
        attr_set = true;
    }

    zero_stats_kernel<<<16, 256>>>();
    stats_kernel<<<dim3(BATCH / 128, 64), 128, SMEM_TOTAL>>>(x, w);
    finalize_kernel<<<16, 256>>>(gamma, beta);
    apply_kernel<<<dim3(BATCH / 128, 64), 128, SMEM_TOTAL>>>(x, w, out);
}

// round 6
// speedup vs baseline: 1.3532x; 1.3532x over previous
#include <cuda_runtime.h>
#include <cstdint>

#define BATCH   4096
#define IN_DIM  4096
#define OUT_DIM 4096
#define BN_EPS  1e-3f

#define XS_STRIDE 68   // words; rows stride 272B -> ldmatrix phase conflict-free
#define BS_STRIDE 72   // words; 8*tig+gid bank perm -> conflict-free B frags

// SMEM (dynamic): Xs[128][68] u32 | Bs[64][72] u32 | bias_s[64] f32
#define XS_OFF   0
#define BS_OFF   (128 * XS_STRIDE * 4)
#define BIAS_OFF (BS_OFF + 64 * BS_STRIDE * 4)
#define SMEM_TOTAL (BIAS_OFF + 64 * 4)

// ---------------- scratch ---------------------------------------------------
__device__ float g_sum[OUT_DIM];
__device__ float g_sumsq[OUT_DIM];
__device__ float g_scale[OUT_DIM];
__device__ float g_shift[OUT_DIM];

__device__ __forceinline__ uint32_t smem_u32(const void* p) {
    uint32_t a;
    asm("{ .reg .u64 t; cvta.to.shared.u64 t, %1; cvt.u32.u64 %0, t; }" : "=r"(a) : "l"(p));
    return a;
}
__device__ __forceinline__ uint32_t f2tf32(float f) {
    uint32_t r;
    asm("cvt.rna.tf32.f32 %0, %1;" : "=r"(r) : "f"(f));
    return r;
}
__device__ __forceinline__ void cp_async16(uint32_t dst, const void* src) {
    asm volatile("cp.async.cg.shared.global [%0], [%1], 16;" :: "r"(dst), "l"(src));
}
__device__ __forceinline__ void ldsm_x4(uint32_t a[4], uint32_t addr) {
    asm volatile("ldmatrix.sync.aligned.m8n8.x4.shared.b16 {%0,%1,%2,%3}, [%4];"
                 : "=r"(a[0]), "=r"(a[1]), "=r"(a[2]), "=r"(a[3]) : "r"(addr));
}
__device__ __forceinline__ void mma_tf32(float c[4], const uint32_t a[4],
                                         const uint32_t b[2]) {
    asm volatile(
        "mma.sync.aligned.m16n8k8.row.col.f32.tf32.tf32.f32 "
        "{%0,%1,%2,%3}, {%4,%5,%6,%7}, {%8,%9}, {%0,%1,%2,%3};"
        : "+f"(c[0]), "+f"(c[1]), "+f"(c[2]), "+f"(c[3])
        : "r"(a[0]), "r"(a[1]), "r"(a[2]), "r"(a[3]), "r"(b[0]), "r"(b[1]));
}

// ---------------- kernels ---------------------------------------------------
__global__ void zero_stats_kernel() {
    int i = blockIdx.x * blockDim.x + threadIdx.x;
    if (i < OUT_DIM) { g_sum[i] = 0.f; g_sumsq[i] = 0.f; }
}

__global__ __launch_bounds__(128) void gemm_stats_kernel(
    const float* __restrict__ x, const float* __restrict__ w,
    const float* __restrict__ bias, float* __restrict__ out)
{
    extern __shared__ char smem[];
    uint32_t* Bs = (uint32_t*)(smem + BS_OFF);
    float* bias_s = (float*)(smem + BIAS_OFF);
    const uint32_t smem_base = smem_u32(smem);

    const int tid  = threadIdx.x;
    const int wid  = tid >> 5;
    const int lane = tid & 31;
    const int gid  = lane >> 2;
    const int tig  = lane & 3;
    const int s       = blockIdx.y;
    const int rowBase = blockIdx.x * 128;

    // ---- X tile via cp.async (raw f32; tf32 HW truncation) ----
    #pragma unroll
    for (int i = 0; i < 16; i++) {
        int idx = i * 128 + tid;
        int row = idx >> 4;
        int c4  = idx & 15;
        cp_async16(smem_base + XS_OFF + (row * XS_STRIDE + c4 * 4) * 4,
                   x + (size_t)(rowBase + row) * IN_DIM + s * 64 + c4 * 4);
    }
    asm volatile("cp.async.commit_group;" ::: "memory");

    // ---- W block (LDG + exact tf32 rounding + STS), overlaps cp.async ----
    #pragma unroll
    for (int i = 0; i < 8; i++) {
        int idx = i * 128 + tid;
        int k  = idx >> 4;
        int c4 = idx & 15;
        float4 v = *(const float4*)(w + (size_t)(s * 64 + k) * OUT_DIM + s * 64 + c4 * 4);
        uint32_t* d = Bs + k * BS_STRIDE + c4 * 4;
        d[0] = f2tf32(v.x); d[1] = f2tf32(v.y); d[2] = f2tf32(v.z); d[3] = f2tf32(v.w);
    }
    if (tid < 16) {
        float4 v = *(const float4*)(bias + s * 64 + tid * 4);
        *(float4*)(bias_s + tid * 4) = v;
    }
    asm volatile("cp.async.wait_group 0;" ::: "memory");
    __syncthreads();

    // ---- per-lane ldmatrix base addresses for A frags ----
    const int quad = lane >> 3;
    const int lr   = lane & 7;
    uint32_t a_addr[2];
    #pragma unroll
    for (int mc = 0; mc < 2; mc++) {
        int r  = wid * 32 + mc * 16 + (quad & 1) * 8 + lr;
        int cw = (quad >> 1) * 4;
        a_addr[mc] = smem_base + XS_OFF + (r * XS_STRIDE + cw) * 4;
    }

    // ---- tensor-core mainloop ----
    float c[2][8][4];
    #pragma unroll
    for (int mc = 0; mc < 2; mc++)
        #pragma unroll
        for (int nc = 0; nc < 8; nc++)
            #pragma unroll
            for (int q = 0; q < 4; q++)
                c[mc][nc][q] = 0.f;

    #pragma unroll
    for (int kc = 0; kc < 8; kc++) {
        const int k0 = kc * 8;
        uint32_t a[2][4];
        ldsm_x4(a[0], a_addr[0] + k0 * 4);
        ldsm_x4(a[1], a_addr[1] + k0 * 4);
        uint32_t b[8][2];
        #pragma unroll
        for (int nc = 0; nc < 8; nc++) {
            b[nc][0] = Bs[(k0 + tig) * BS_STRIDE + nc * 8 + gid];
            b[nc][1] = Bs[(k0 + tig + 4) * BS_STRIDE + nc * 8 + gid];
        }
        #pragma unroll
        for (int mc = 0; mc < 2; mc++)
            #pragma unroll
            for (int nc = 0; nc < 8; nc++)
                mma_tf32(c[mc][nc], a[mc], b[nc]);
    }
    __syncthreads();   // done reading Xs/Bs; reuse Xs as stage

    // ---- bias add + stage to SMEM ----
    float* stage = (float*)(smem + XS_OFF);
    #pragma unroll
    for (int nc = 0; nc < 8; nc++) {
        const int col = nc * 8 + 2 * tig;
        const float bx = bias_s[col], by = bias_s[col + 1];
        #pragma unroll
        for (int mc = 0; mc < 2; mc++) {
            const int r = wid * 32 + mc * 16 + gid;
            stage[r * XS_STRIDE + col]           = c[mc][nc][0] + bx;
            stage[r * XS_STRIDE + col + 1]       = c[mc][nc][1] + by;
            stage[(r + 8) * XS_STRIDE + col]     = c[mc][nc][2] + bx;
            stage[(r + 8) * XS_STRIDE + col + 1] = c[mc][nc][3] + by;
        }
    }
    __syncthreads();

    // ---- coalesced store of pre-BN tile ----
    #pragma unroll
    for (int i = 0; i < 16; i++) {
        int idx = i * 128 + tid;
        int row = idx >> 4;
        int c4  = idx & 15;
        float4 v = *(const float4*)(stage + row * XS_STRIDE + c4 * 4);
        *(float4*)(out + (size_t)(rowBase + row) * OUT_DIM + s * 64 + c4 * 4) = v;
    }
    // ---- per-column partial stats ----
    {
        const int j = tid & 63;
        const int half = tid >> 6;
        float sm = 0.f, sq = 0.f;
        #pragma unroll 8
        for (int rr = 0; rr < 64; rr++) {
            float v = stage[(half * 64 + rr) * XS_STRIDE + j];
            sm += v;
            sq = fmaf(v, v, sq);
        }
        atomicAdd(&g_sum[s * 64 + j], sm);
        atomicAdd(&g_sumsq[s * 64 + j], sq);
    }
}

__global__ void finalize_kernel(const float* __restrict__ gamma,
                                const float* __restrict__ beta) {
    int j = blockIdx.x * blockDim.x + threadIdx.x;
    if (j < OUT_DIM) {
        const float invB = 1.0f / (float)BATCH;
        float mean = g_sum[j] * invB;
        float var  = fmaxf(g_sumsq[j] * invB - mean * mean, 0.f);
        float sc   = gamma[j] * rsqrtf(var + BN_EPS);
        g_scale[j] = sc;
        g_shift[j] = fmaf(-mean, sc, beta[j]);
    }
}

__global__ __launch_bounds__(256) void pass2_kernel(float* __restrict__ out) {
    int base = blockIdx.x * 512 + threadIdx.x;
    #pragma unroll
    for (int t = 0; t < 2; t++) {
        int idx = base + t * 256;
        int j4  = idx & (OUT_DIM / 4 - 1);
        float4 v  = ((const float4*)out)[idx];
        float4 sc = ((const float4*)g_scale)[j4];
        float4 sh = ((const float4*)g_shift)[j4];
        v.x = fmaxf(fmaf(v.x, sc.x, sh.x), 0.f);
        v.y = fmaxf(fmaf(v.y, sc.y, sh.y), 0.f);
        v.z = fmaxf(fmaf(v.z, sc.z, sh.z), 0.f);
        v.w = fmaxf(fmaf(v.w, sc.w, sh.w), 0.f);
        ((float4*)out)[idx] = v;
    }
}

extern "C" void kernel_launch(void* const* d_in, const int* in_sizes, int n_in,
                              void* d_out, int out_size) {
    const float* x     = (const float*)d_in[0];
    const float* w     = (const float*)d_in[1];
    const float* bias  = (const float*)d_in[2];
    const float* gamma = (const float*)d_in[3];
    const float* beta  = (const float*)d_in[4];
    float* out = (float*)d_out;

    static bool attr_set = false;
    if (!attr_set) {
        cudaFuncSetAttribute(gemm_stats_kernel,
                             cudaFuncAttributeMaxDynamicSharedMemorySize, SMEM_TOTAL);
        attr_set = true;
    }

    zero_stats_kernel<<<16, 256>>>();
    gemm_stats_kernel<<<dim3(BATCH / 128, 64), 128, SMEM_TOTAL>>>(x, w, bias, out);
    finalize_kernel<<<16, 256>>>(gamma, beta);
    pass2_kernel<<<(BATCH * OUT_DIM / 4) / 512, 256>>>(out);
}

// round 7
// speedup vs baseline: 1.4000x; 1.0346x over previous
#include <cuda_runtime.h>
#include <cuda_fp16.h>
#include <cstdint>

#define BATCH   4096
#define IN_DIM  4096
#define OUT_DIM 4096
#define BN_EPS  1e-3f

#define XS_STRIDE 68   // words; rows stride 272B -> ldmatrix phase conflict-free
#define BS_STRIDE 72   // words; 8*tig+gid bank perm -> conflict-free B frags

// SMEM (dynamic): Xs[128][68] u32 | Bs[64][72] u32 | bias_s[64] f32
#define XS_OFF   0
#define BS_OFF   (128 * XS_STRIDE * 4)
#define BIAS_OFF (BS_OFF + 64 * BS_STRIDE * 4)
#define SMEM_TOTAL (BIAS_OFF + 64 * 4)

// ---------------- scratch ---------------------------------------------------
__device__ float g_sum[OUT_DIM];
__device__ float g_sumsq[OUT_DIM];
__device__ float g_scale[OUT_DIM];
__device__ float g_shift[OUT_DIM];
__device__ uint2 g_mid[BATCH * OUT_DIM / 4];   // fp16 pre-BN intermediate (33MB)

__device__ __forceinline__ uint32_t smem_u32(const void* p) {
    uint32_t a;
    asm("{ .reg .u64 t; cvta.to.shared.u64 t, %1; cvt.u32.u64 %0, t; }" : "=r"(a) : "l"(p));
    return a;
}
__device__ __forceinline__ uint32_t f2tf32(float f) {
    uint32_t r;
    asm("cvt.rna.tf32.f32 %0, %1;" : "=r"(r) : "f"(f));
    return r;
}
__device__ __forceinline__ void cp_async16(uint32_t dst, const void* src) {
    asm volatile("cp.async.cg.shared.global [%0], [%1], 16;" :: "r"(dst), "l"(src));
}
__device__ __forceinline__ void ldsm_x4(uint32_t a[4], uint32_t addr) {
    asm volatile("ldmatrix.sync.aligned.m8n8.x4.shared.b16 {%0,%1,%2,%3}, [%4];"
                 : "=r"(a[0]), "=r"(a[1]), "=r"(a[2]), "=r"(a[3]) : "r"(addr));
}
__device__ __forceinline__ void mma_tf32(float c[4], const uint32_t a[4],
                                         const uint32_t b[2]) {
    asm volatile(
        "mma.sync.aligned.m16n8k8.row.col.f32.tf32.tf32.f32 "
        "{%0,%1,%2,%3}, {%4,%5,%6,%7}, {%8,%9}, {%0,%1,%2,%3};"
        : "+f"(c[0]), "+f"(c[1]), "+f"(c[2]), "+f"(c[3])
        : "r"(a[0]), "r"(a[1]), "r"(a[2]), "r"(a[3]), "r"(b[0]), "r"(b[1]));
}

// ---------------- kernels ---------------------------------------------------
__global__ void zero_stats_kernel() {
    int i = blockIdx.x * blockDim.x + threadIdx.x;
    if (i < OUT_DIM) { g_sum[i] = 0.f; g_sumsq[i] = 0.f; }
}

__global__ __launch_bounds__(128) void gemm_stats_kernel(
    const float* __restrict__ x, const float* __restrict__ w,
    const float* __restrict__ bias)
{
    extern __shared__ char smem[];
    uint32_t* Bs = (uint32_t*)(smem + BS_OFF);
    float* bias_s = (float*)(smem + BIAS_OFF);
    const uint32_t smem_base = smem_u32(smem);

    const int tid  = threadIdx.x;
    const int wid  = tid >> 5;
    const int lane = tid & 31;
    const int gid  = lane >> 2;
    const int tig  = lane & 3;
    const int s       = blockIdx.y;
    const int rowBase = blockIdx.x * 128;

    // ---- X tile via cp.async (raw f32; tf32 HW truncation) ----
    #pragma unroll
    for (int i = 0; i < 16; i++) {
        int idx = i * 128 + tid;
        int row = idx >> 4;
        int c4  = idx & 15;
        cp_async16(smem_base + XS_OFF + (row * XS_STRIDE + c4 * 4) * 4,
                   x + (size_t)(rowBase + row) * IN_DIM + s * 64 + c4 * 4);
    }
    asm volatile("cp.async.commit_group;" ::: "memory");

    // ---- W block (LDG + exact tf32 rounding + STS) ----
    #pragma unroll
    for (int i = 0; i < 8; i++) {
        int idx = i * 128 + tid;
        int k  = idx >> 4;
        int c4 = idx & 15;
        float4 v = *(const float4*)(w + (size_t)(s * 64 + k) * OUT_DIM + s * 64 + c4 * 4);
        uint32_t* d = Bs + k * BS_STRIDE + c4 * 4;
        d[0] = f2tf32(v.x); d[1] = f2tf32(v.y); d[2] = f2tf32(v.z); d[3] = f2tf32(v.w);
    }
    if (tid < 16) {
        float4 v = *(const float4*)(bias + s * 64 + tid * 4);
        *(float4*)(bias_s + tid * 4) = v;
    }
    asm volatile("cp.async.wait_group 0;" ::: "memory");
    __syncthreads();

    // ---- per-lane ldmatrix base addresses for A frags ----
    const int quad = lane >> 3;
    const int lr   = lane & 7;
    uint32_t a_addr[2];
    #pragma unroll
    for (int mc = 0; mc < 2; mc++) {
        int r  = wid * 32 + mc * 16 + (quad & 1) * 8 + lr;
        int cw = (quad >> 1) * 4;
        a_addr[mc] = smem_base + XS_OFF + (r * XS_STRIDE + cw) * 4;
    }

    // ---- tensor-core mainloop ----
    float c[2][8][4];
    #pragma unroll
    for (int mc = 0; mc < 2; mc++)
        #pragma unroll
        for (int nc = 0; nc < 8; nc++)
            #pragma unroll
            for (int q = 0; q < 4; q++)
                c[mc][nc][q] = 0.f;

    #pragma unroll
    for (int kc = 0; kc < 8; kc++) {
        const int k0 = kc * 8;
        uint32_t a[2][4];
        ldsm_x4(a[0], a_addr[0] + k0 * 4);
        ldsm_x4(a[1], a_addr[1] + k0 * 4);
        uint32_t b[8][2];
        #pragma unroll
        for (int nc = 0; nc < 8; nc++) {
            b[nc][0] = Bs[(k0 + tig) * BS_STRIDE + nc * 8 + gid];
            b[nc][1] = Bs[(k0 + tig + 4) * BS_STRIDE + nc * 8 + gid];
        }
        #pragma unroll
        for (int mc = 0; mc < 2; mc++)
            #pragma unroll
            for (int nc = 0; nc < 8; nc++)
                mma_tf32(c[mc][nc], a[mc], b[nc]);
    }
    __syncthreads();   // done reading Xs/Bs; reuse Xs as stage

    // ---- bias add + stage to SMEM ----
    float* stage = (float*)(smem + XS_OFF);
    #pragma unroll
    for (int nc = 0; nc < 8; nc++) {
        const int col = nc * 8 + 2 * tig;
        const float bx = bias_s[col], by = bias_s[col + 1];
        #pragma unroll
        for (int mc = 0; mc < 2; mc++) {
            const int r = wid * 32 + mc * 16 + gid;
            stage[r * XS_STRIDE + col]           = c[mc][nc][0] + bx;
            stage[r * XS_STRIDE + col + 1]       = c[mc][nc][1] + by;
            stage[(r + 8) * XS_STRIDE + col]     = c[mc][nc][2] + bx;
            stage[(r + 8) * XS_STRIDE + col + 1] = c[mc][nc][3] + by;
        }
    }
    __syncthreads();

    // ---- coalesced fp16 store of pre-BN tile ----
    #pragma unroll
    for (int i = 0; i < 16; i++) {
        int idx = i * 128 + tid;
        int row = idx >> 4;
        int c4  = idx & 15;
        float4 v = *(const float4*)(stage + row * XS_STRIDE + c4 * 4);
        __half2 h0 = __floats2half2_rn(v.x, v.y);
        __half2 h1 = __floats2half2_rn(v.z, v.w);
        uint2 u;
        u.x = *(uint32_t*)&h0;
        u.y = *(uint32_t*)&h1;
        g_mid[((size_t)(rowBase + row) * OUT_DIM + s * 64 + c4 * 4) >> 2] = u;
    }
    // ---- per-column partial stats ----
    {
        const int j = tid & 63;
        const int half = tid >> 6;
        float sm = 0.f, sq = 0.f;
        #pragma unroll 8
        for (int rr = 0; rr < 64; rr++) {
            float v = stage[(half * 64 + rr) * XS_STRIDE + j];
            sm += v;
            sq = fmaf(v, v, sq);
        }
        atomicAdd(&g_sum[s * 64 + j], sm);
        atomicAdd(&g_sumsq[s * 64 + j], sq);
    }
}

__global__ void finalize_kernel(const float* __restrict__ gamma,
                                const float* __restrict__ beta) {
    int j = blockIdx.x * blockDim.x + threadIdx.x;
    if (j < OUT_DIM) {
        const float invB = 1.0f / (float)BATCH;
        float mean = g_sum[j] * invB;
        float var  = fmaxf(g_sumsq[j] * invB - mean * mean, 0.f);
        float sc   = gamma[j] * rsqrtf(var + BN_EPS);
        g_scale[j] = sc;
        g_shift[j] = fmaf(-mean, sc, beta[j]);
    }
}

__global__ __launch_bounds__(256) void pass2_kernel(float* __restrict__ out) {
    int base = blockIdx.x * 512 + threadIdx.x;
    #pragma unroll
    for (int t = 0; t < 2; t++) {
        int idx = base + t * 256;        // float4 index
        int j4  = idx & (OUT_DIM / 4 - 1);
        uint2 u = g_mid[idx];
        float2 f0 = __half22float2(*(__half2*)&u.x);
        float2 f1 = __half22float2(*(__half2*)&u.y);
        float4 sc = ((const float4*)g_scale)[j4];
        float4 sh = ((const float4*)g_shift)[j4];
        float4 v;
        v.x = fmaxf(fmaf(f0.x, sc.x, sh.x), 0.f);
        v.y = fmaxf(fmaf(f0.y, sc.y, sh.y), 0.f);
        v.z = fmaxf(fmaf(f1.x, sc.z, sh.z), 0.f);
        v.w = fmaxf(fmaf(f1.y, sc.w, sh.w), 0.f);
        ((float4*)out)[idx] = v;
    }
}

extern "C" void kernel_launch(void* const* d_in, const int* in_sizes, int n_in,
                              void* d_out, int out_size) {
    const float* x     = (const float*)d_in[0];
    const float* w     = (const float*)d_in[1];
    const float* bias  = (const float*)d_in[2];
    const float* gamma = (const float*)d_in[3];
    const float* beta  = (const float*)d_in[4];
    float* out = (float*)d_out;

    static bool attr_set = false;
    if (!attr_set) {
        cudaFuncSetAttribute(gemm_stats_kernel,
                             cudaFuncAttributeMaxDynamicSharedMemorySize, SMEM_TOTAL);
        attr_set = true;
    }

    zero_stats_kernel<<<16, 256>>>();
    gemm_stats_kernel<<<dim3(BATCH / 128, 64), 128, SMEM_TOTAL>>>(x, w, bias);
    finalize_kernel<<<16, 256>>>(gamma, beta);
    pass2_kernel<<<(BATCH * OUT_DIM / 4) / 512, 256>>>(out);
}